// round 7
// baseline (speedup 1.0000x reference)
#include <cuda_runtime.h>
#include <cuda_fp16.h>
#include <math.h>
#include <stdint.h>

// Problem dims
#define SEQ    4096
#define IDIM   2048
#define HDIM   2048
#define GROWS  8192   // 4*HDIM, PyTorch gate order i,f,g,o
#define OUTD   2048

// Persistent recurrence kernel config
#define UPC      14
#define NCTA     147
#define RTHREADS 256
#define MAXROWS  (4*UPC)
#define SW_BYTES (MAXROWS*HDIM*sizeof(__half))   // 229376 B

// mma.sync GEMM config
#define BM 128
#define BN 128
#define BK 32
#define NCH    (IDIM/BK)          // 64 k-chunks
#define STAGES 4
#define APAD   40                 // halves per SMEM row (32 + 8 pad) -> 80B stride
#define STG_A  (BM*APAD*2)        // 10240 B
#define STG_B  (2*STG_A)          // 20480 B per stage (A then B)
#define GEMM_SMEM (STAGES*STG_B)  // 81920 B

// -------- device scratch (static allocation only) --------
__device__ float    g_xg[(size_t)SEQ * GROWS];   // 128 MB
__device__ __half   g_xh[(size_t)SEQ * IDIM];    // 16 MB  x in fp16
__device__ __half   g_wh[(size_t)GROWS * IDIM];  // 32 MB  W_ih in fp16
__device__ float    g_h[2][HDIM];
__device__ unsigned g_flag[NCTA * 32];           // per-CTA step flags, 128B apart

// ---------------- PTX helpers (all sm_80+; no arch-suffix features) ----------
__device__ __forceinline__ uint32_t smem_u32(const void* p) {
    return (uint32_t)__cvta_generic_to_shared(p);
}
__device__ __forceinline__ void cp_async16(uint32_t dst, const void* src) {
    asm volatile("cp.async.cg.shared.global [%0], [%1], 16;" :: "r"(dst), "l"(src));
}
__device__ __forceinline__ void ldmatrix_x4(uint32_t* r, uint32_t addr) {
    asm volatile("ldmatrix.sync.aligned.m8n8.x4.shared.b16 {%0,%1,%2,%3}, [%4];"
                 : "=r"(r[0]), "=r"(r[1]), "=r"(r[2]), "=r"(r[3]) : "r"(addr));
}
__device__ __forceinline__ void mma16816(float* c, const uint32_t* a,
                                         uint32_t b0, uint32_t b1) {
    asm volatile(
        "mma.sync.aligned.m16n8k16.row.col.f32.f16.f16.f32 "
        "{%0,%1,%2,%3}, {%4,%5,%6,%7}, {%8,%9}, {%0,%1,%2,%3};"
        : "+f"(c[0]), "+f"(c[1]), "+f"(c[2]), "+f"(c[3])
        : "r"(a[0]), "r"(a[1]), "r"(a[2]), "r"(a[3]), "r"(b0), "r"(b1));
}

// ============================================================================
// Kernel 0: fp32 -> fp16 conversion (x and W_ih)
// ============================================================================
__global__ void __launch_bounds__(256)
f2h_kernel(const float* __restrict__ src, __half* __restrict__ dst, int n)
{
    int i = (blockIdx.x * 256 + threadIdx.x) * 8;
    if (i >= n) return;
    const float4 a = *(const float4*)(src + i);
    const float4 b = *(const float4*)(src + i + 4);
    __half2 h0 = __floats2half2_rn(a.x, a.y);
    __half2 h1 = __floats2half2_rn(a.z, a.w);
    __half2 h2 = __floats2half2_rn(b.x, b.y);
    __half2 h3 = __floats2half2_rn(b.z, b.w);
    uint4 o;
    o.x = *(uint32_t*)&h0; o.y = *(uint32_t*)&h1;
    o.z = *(uint32_t*)&h2; o.w = *(uint32_t*)&h3;
    *(uint4*)(dst + i) = o;
}

// ============================================================================
// Kernel 1: xg = x @ W_ih^T + b_ih + b_hh  via mma.sync.m16n8k16 (fp16->fp32).
// 128x128 tile / CTA, 8 warps of 64x32, 4-stage cp.async pipeline over K.
// Both operands K-major ("NT" gemm) -> row.col mma with plain ldmatrix.
// ============================================================================
__global__ void __launch_bounds__(256, 1)
gemm_xg_mma(const float* __restrict__ b1, const float* __restrict__ b2)
{
    extern __shared__ char dynsmem[];
    __shared__ float s_bias[BN];

    const int tid    = threadIdx.x;
    const int lane   = tid & 31;
    const int wid    = tid >> 5;
    const int warp_m = wid >> 2;            // 0..1
    const int warp_n = wid & 3;             // 0..3
    const int mw     = warp_m * 64;
    const int nb     = warp_n * 32;
    const int n0     = blockIdx.x * BN;
    const int m0     = blockIdx.y * BM;

    const uint32_t sm0 = smem_u32(dynsmem);

    if (tid < BN) s_bias[tid] = b1[n0 + tid] + b2[n0 + tid];

    const __half* gA = g_xh + (size_t)m0 * IDIM;
    const __half* gB = g_wh + (size_t)n0 * IDIM;

    // stage load: 1024 x 16B segments (A 512 + B 512), 4 per thread
    auto load_chunk = [&](int kc) {
        const uint32_t base = sm0 + (uint32_t)(kc & (STAGES - 1)) * STG_B;
        const int k0 = kc * BK;
#pragma unroll
        for (int part = 0; part < 4; ++part) {
            const int idx = part * 256 + tid;           // 0..1023
            const int row = (idx >> 2) & 127;
            const int seg = idx & 3;
            const uint32_t doff = (uint32_t)(row * (APAD * 2) + seg * 16);
            if (idx < 512)
                cp_async16(base + doff, gA + (size_t)row * IDIM + k0 + seg * 8);
            else
                cp_async16(base + STG_A + doff, gB + (size_t)row * IDIM + k0 + seg * 8);
        }
        asm volatile("cp.async.commit_group;" ::: "memory");
    };

    float acc[4][4][4];
#pragma unroll
    for (int mi = 0; mi < 4; ++mi)
#pragma unroll
        for (int ni = 0; ni < 4; ++ni)
#pragma unroll
            for (int q = 0; q < 4; ++q) acc[mi][ni][q] = 0.f;

    load_chunk(0);
    load_chunk(1);
    load_chunk(2);

    for (int kc = 0; kc < NCH; ++kc) {
        const int pf = kc + STAGES - 1;
        if (pf < NCH) load_chunk(pf);

        // guarantee chunk kc complete: wait until <= (#newer chunks) pending
        if (kc <= NCH - STAGES)
            asm volatile("cp.async.wait_group %0;" :: "n"(STAGES - 1) : "memory");
        else if (kc == NCH - 3)
            asm volatile("cp.async.wait_group 2;" ::: "memory");
        else if (kc == NCH - 2)
            asm volatile("cp.async.wait_group 1;" ::: "memory");
        else
            asm volatile("cp.async.wait_group 0;" ::: "memory");
        __syncthreads();

        const uint32_t as_ = sm0 + (uint32_t)(kc & (STAGES - 1)) * STG_B;
        const uint32_t bs_ = as_ + STG_A;

#pragma unroll
        for (int s = 0; s < 2; ++s) {               // two k16 steps
            uint32_t af[4][4];
#pragma unroll
            for (int mi = 0; mi < 4; ++mi) {
                const uint32_t addr = as_
                    + (uint32_t)(mw + mi * 16 + (lane & 15)) * (APAD * 2)
                    + (uint32_t)(s * 16 + ((lane >> 4) << 3)) * 2;
                ldmatrix_x4(af[mi], addr);
            }
            uint32_t bf[2][4];
#pragma unroll
            for (int g = 0; g < 2; ++g) {
                const uint32_t addr = bs_
                    + (uint32_t)(nb + g * 16 + (lane & 7) + (((lane >> 4) & 1) << 3)) * (APAD * 2)
                    + (uint32_t)(s * 16 + (((lane >> 3) & 1) << 3)) * 2;
                ldmatrix_x4(bf[g], addr);
            }
#pragma unroll
            for (int mi = 0; mi < 4; ++mi)
#pragma unroll
                for (int ni = 0; ni < 4; ++ni)
                    mma16816(acc[mi][ni], af[mi],
                             bf[ni >> 1][(ni & 1) * 2],
                             bf[ni >> 1][(ni & 1) * 2 + 1]);
        }
        __syncthreads();   // all warps done reading before this stage is refilled
    }

    // epilogue: add bias, write fp32 to g_xg
#pragma unroll
    for (int mi = 0; mi < 4; ++mi) {
        const int r0 = m0 + mw + mi * 16 + (lane >> 2);
#pragma unroll
        for (int ni = 0; ni < 4; ++ni) {
            const int c = nb + ni * 8 + (lane & 3) * 2;
            const float bb0 = s_bias[c];
            const float bb1 = s_bias[c + 1];
            float2 v0, v1;
            v0.x = acc[mi][ni][0] + bb0; v0.y = acc[mi][ni][1] + bb1;
            v1.x = acc[mi][ni][2] + bb0; v1.y = acc[mi][ni][3] + bb1;
            *(float2*)&g_xg[(size_t)r0 * GROWS + n0 + c]       = v0;
            *(float2*)&g_xg[(size_t)(r0 + 8) * GROWS + n0 + c] = v1;
        }
    }
}

// ============================================================================
// Kernel 2: persistent LSTM recurrence. W_hh fp16 in SMEM, h broadcast via
// global, distributed per-CTA flag barrier (no contended atomic).
// ============================================================================
__global__ void __launch_bounds__(RTHREADS, 1)
lstm_persistent(const float* __restrict__ W_hh)
{
    extern __shared__ __half sw[];
    __shared__ float s_gate[MAXROWS];
    __shared__ float s_c[UPC];
    __shared__ unsigned s_base;

    const int tid  = threadIdx.x;
    const int wid  = tid >> 5;
    const int lane = tid & 31;
    const int cta  = blockIdx.x;
    const int u0   = cta * UPC;
    const int nu   = (HDIM - u0 < UPC) ? (HDIM - u0) : UPC;
    const int nrows = 4 * nu;

    // one-time: W_hh rows -> SMEM fp16
    for (int e = tid * 4; e < nrows * HDIM; e += RTHREADS * 4) {
        int r    = e / HDIM;
        int k    = e - r * HDIM;
        int gate = r / nu;
        int u    = r - gate * nu;
        const float4 v = *(const float4*)&W_hh[(size_t)(gate * HDIM + u0 + u) * HDIM + k];
        __half2* dst = (__half2*)&sw[r * HDIM + k];
        dst[0] = __floats2half2_rn(v.x, v.y);
        dst[1] = __floats2half2_rn(v.z, v.w);
    }
    if (tid < UPC)     s_c[tid]    = 0.f;
    if (tid < MAXROWS) s_gate[tid] = 0.f;
    if (tid == 0)      s_base = *(volatile unsigned*)&g_flag[cta * 32];
    __syncthreads();
    const unsigned base = s_base;

    for (int t = 0; t < SEQ; ++t) {
        // prefetch xg (independent of h)
        float xgv0 = 0.f, xgv1 = 0.f, xgv2 = 0.f, xgv3 = 0.f;
        if (tid < nu) {
            const float* xp = g_xg + (size_t)t * GROWS + u0 + tid;
            xgv0 = xp[0 * HDIM];
            xgv1 = xp[1 * HDIM];
            xgv2 = xp[2 * HDIM];
            xgv3 = xp[3 * HDIM];
        }

        if (t > 0) {
            __syncthreads();   // all of step t-1's h writes done CTA-wide
            if (wid == 0) {
                const unsigned target = base + (unsigned)t;
                if (lane == 0) {
                    __threadfence();                       // release our h slice
                    *(volatile unsigned*)&g_flag[cta * 32] = target;
                }
                bool ok;
                do {
                    unsigned mn = 0xffffffffu;
                    for (int j = lane; j < NCTA; j += 32)
                        mn = min(mn, *(volatile unsigned*)&g_flag[j * 32]);
                    ok = ((int)(mn - target) >= 0);
                } while (!__all_sync(0xffffffffu, ok));
                if (lane == 0) __threadfence();            // CCTL.IVALL: fresh L1
            }
            __syncthreads();

            // load full h into registers (L1-shared across warps)
            float hreg[64];
            const float* hb = g_h[t & 1];
#pragma unroll
            for (int c = 0; c < 8; ++c) {
                const float4 v0 = *(const float4*)&hb[c * 256 + lane * 8];
                const float4 v1 = *(const float4*)&hb[c * 256 + lane * 8 + 4];
                hreg[c * 8 + 0] = v0.x; hreg[c * 8 + 1] = v0.y;
                hreg[c * 8 + 2] = v0.z; hreg[c * 8 + 3] = v0.w;
                hreg[c * 8 + 4] = v1.x; hreg[c * 8 + 5] = v1.y;
                hreg[c * 8 + 6] = v1.z; hreg[c * 8 + 7] = v1.w;
            }

            for (int r = wid; r < nrows; r += 8) {
                const __half* wr = sw + r * HDIM;
                float a0 = 0.f, a1 = 0.f, a2 = 0.f, a3 = 0.f;
#pragma unroll
                for (int c = 0; c < 8; ++c) {
                    const uint4 wv = *(const uint4*)(wr + c * 256 + lane * 8);
                    const __half2 p0 = *reinterpret_cast<const __half2*>(&wv.x);
                    const __half2 p1 = *reinterpret_cast<const __half2*>(&wv.y);
                    const __half2 p2 = *reinterpret_cast<const __half2*>(&wv.z);
                    const __half2 p3 = *reinterpret_cast<const __half2*>(&wv.w);
                    float2 f;
                    f = __half22float2(p0);
                    a0 = fmaf(f.x, hreg[c * 8 + 0], a0);
                    a1 = fmaf(f.y, hreg[c * 8 + 1], a1);
                    f = __half22float2(p1);
                    a2 = fmaf(f.x, hreg[c * 8 + 2], a2);
                    a3 = fmaf(f.y, hreg[c * 8 + 3], a3);
                    f = __half22float2(p2);
                    a0 = fmaf(f.x, hreg[c * 8 + 4], a0);
                    a1 = fmaf(f.y, hreg[c * 8 + 5], a1);
                    f = __half22float2(p3);
                    a2 = fmaf(f.x, hreg[c * 8 + 6], a2);
                    a3 = fmaf(f.y, hreg[c * 8 + 7], a3);
                }
                float acc = (a0 + a1) + (a2 + a3);
#pragma unroll
                for (int off = 16; off; off >>= 1)
                    acc += __shfl_xor_sync(0xffffffffu, acc, off);
                if (lane == 0) s_gate[r] = acc;
            }
        }
        __syncthreads();

        if (tid < nu) {
            const float gi = xgv0 + s_gate[0 * nu + tid];
            const float gf = xgv1 + s_gate[1 * nu + tid];
            const float gg = xgv2 + s_gate[2 * nu + tid];
            const float go = xgv3 + s_gate[3 * nu + tid];
            const float ig = 1.f / (1.f + expf(-gi));
            const float fg = 1.f / (1.f + expf(-gf));
            const float g2 = tanhf(gg);
            const float og = 1.f / (1.f + expf(-go));
            const float cc = fg * s_c[tid] + ig * g2;
            s_c[tid] = cc;
            g_h[(t + 1) & 1][u0 + tid] = og * tanhf(cc);
        }
    }
    // no final barrier needed: flags are monotonic; each CTA reads its OWN
    // flag (= base + SEQ - 1) as the next replay's base.
}

// ============================================================================
// Kernel 3: out = h_last @ W_fc^T + b_fc   (h_last in g_h[0]; SEQ even)
// ============================================================================
__global__ void __launch_bounds__(256)
fc_kernel(const float* __restrict__ Wfc, const float* __restrict__ bfc,
          float* __restrict__ out)
{
    const int o    = blockIdx.x * 8 + (threadIdx.x >> 5);
    const int lane = threadIdx.x & 31;
    const float* hb = g_h[0];
    const float* wr = Wfc + (size_t)o * HDIM;
    float acc = 0.f;
#pragma unroll
    for (int i = 0; i < 16; ++i) {
        const int k = i * 128 + lane * 4;
        const float4 w  = *(const float4*)&wr[k];
        const float4 h4 = *(const float4*)&hb[k];
        acc += w.x * h4.x + w.y * h4.y + w.z * h4.z + w.w * h4.w;
    }
#pragma unroll
    for (int off = 16; off; off >>= 1)
        acc += __shfl_xor_sync(0xffffffffu, acc, off);
    if (lane == 0) out[o] = acc + bfc[o];
}

// ============================================================================
extern "C" void kernel_launch(void* const* d_in, const int* in_sizes, int n_in,
                              void* d_out, int out_size)
{
    const float* x   = (const float*)d_in[0];
    const float* Wih = (const float*)d_in[1];
    const float* Whh = (const float*)d_in[2];
    const float* bih = (const float*)d_in[3];
    const float* bhh = (const float*)d_in[4];
    const float* Wfc = (const float*)d_in[5];
    const float* bfc = (const float*)d_in[6];
    float* out = (float*)d_out;

    static __half* p_xh = nullptr;
    static __half* p_wh = nullptr;
    if (!p_xh) {
        cudaGetSymbolAddress((void**)&p_xh, g_xh);
        cudaGetSymbolAddress((void**)&p_wh, g_wh);
        cudaFuncSetAttribute(gemm_xg_mma,
                             cudaFuncAttributeMaxDynamicSharedMemorySize,
                             (int)GEMM_SMEM);
        cudaFuncSetAttribute(lstm_persistent,
                             cudaFuncAttributeMaxDynamicSharedMemorySize,
                             (int)SW_BYTES);
    }

    f2h_kernel<<<(SEQ * IDIM / 8 + 255) / 256, 256>>>(x, p_xh, SEQ * IDIM);
    f2h_kernel<<<(GROWS * IDIM / 8 + 255) / 256, 256>>>(Wih, p_wh, GROWS * IDIM);
    gemm_xg_mma<<<dim3(GROWS / BN, SEQ / BM), 256, GEMM_SMEM>>>(bih, bhh);
    lstm_persistent<<<NCTA, RTHREADS, SW_BYTES>>>(Whh);
    fc_kernel<<<OUTD / 8, 256>>>(Wfc, bfc, out);
}

// round 8
// speedup vs baseline: 1.2821x; 1.2821x over previous
#include <cuda_runtime.h>
#include <cuda_fp16.h>
#include <math.h>
#include <stdint.h>

// Problem dims
#define SEQ    4096
#define IDIM   2048
#define HDIM   2048
#define GROWS  8192   // 4*HDIM, PyTorch gate order i,f,g,o
#define OUTD   2048

// Persistent recurrence kernel config
#define UPC      14
#define NCTA     147
#define RTHREADS 512
#define NWARP    (RTHREADS/32)
#define MAXROWS  (4*UPC)
#define SW_BYTES (MAXROWS*HDIM*sizeof(__half))   // 229376 B

// mma.sync GEMM config
#define BM 128
#define BN 128
#define BK 32
#define NCH    (IDIM/BK)          // 64 k-chunks
#define STAGES 4
#define APAD   40                 // halves per SMEM row (32 + 8 pad) -> 80B stride
#define STG_A  (BM*APAD*2)        // 10240 B
#define STG_B  (2*STG_A)          // 20480 B per stage (A then B)
#define GEMM_SMEM (STAGES*STG_B)  // 81920 B

// -------- device scratch (static allocation only) --------
__device__ float    g_xg[(size_t)SEQ * GROWS];   // 128 MB
__device__ __half   g_xh[(size_t)SEQ * IDIM];    // 16 MB  x in fp16
__device__ __half   g_wh[(size_t)GROWS * IDIM];  // 32 MB  W_ih in fp16
__device__ float    g_h[2][HDIM];
__device__ unsigned g_bar  = 0u;                 // monotonic arrival counter
__device__ unsigned g_base = 0u;                 // epoch base across graph replays

// ---------------- PTX helpers (all sm_80+; no arch-suffix features) ----------
__device__ __forceinline__ uint32_t smem_u32(const void* p) {
    return (uint32_t)__cvta_generic_to_shared(p);
}
__device__ __forceinline__ void cp_async16(uint32_t dst, const void* src) {
    asm volatile("cp.async.cg.shared.global [%0], [%1], 16;" :: "r"(dst), "l"(src));
}
__device__ __forceinline__ void ldmatrix_x4(uint32_t* r, uint32_t addr) {
    asm volatile("ldmatrix.sync.aligned.m8n8.x4.shared.b16 {%0,%1,%2,%3}, [%4];"
                 : "=r"(r[0]), "=r"(r[1]), "=r"(r[2]), "=r"(r[3]) : "r"(addr));
}
__device__ __forceinline__ void mma16816(float* c, const uint32_t* a,
                                         uint32_t b0, uint32_t b1) {
    asm volatile(
        "mma.sync.aligned.m16n8k16.row.col.f32.f16.f16.f32 "
        "{%0,%1,%2,%3}, {%4,%5,%6,%7}, {%8,%9}, {%0,%1,%2,%3};"
        : "+f"(c[0]), "+f"(c[1]), "+f"(c[2]), "+f"(c[3])
        : "r"(a[0]), "r"(a[1]), "r"(a[2]), "r"(a[3]), "r"(b0), "r"(b1));
}

// ============================================================================
// Kernel 0: fp32 -> fp16 conversion (x and W_ih)
// ============================================================================
__global__ void __launch_bounds__(256)
f2h_kernel(const float* __restrict__ src, __half* __restrict__ dst, int n)
{
    int i = (blockIdx.x * 256 + threadIdx.x) * 8;
    if (i >= n) return;
    const float4 a = *(const float4*)(src + i);
    const float4 b = *(const float4*)(src + i + 4);
    __half2 h0 = __floats2half2_rn(a.x, a.y);
    __half2 h1 = __floats2half2_rn(a.z, a.w);
    __half2 h2 = __floats2half2_rn(b.x, b.y);
    __half2 h3 = __floats2half2_rn(b.z, b.w);
    uint4 o;
    o.x = *(uint32_t*)&h0; o.y = *(uint32_t*)&h1;
    o.z = *(uint32_t*)&h2; o.w = *(uint32_t*)&h3;
    *(uint4*)(dst + i) = o;
}

// ============================================================================
// Kernel 1: xg = x @ W_ih^T + b_ih + b_hh  via mma.sync.m16n8k16 (fp16->fp32).
// 128x128 tile / CTA, 8 warps of 64x32, 4-stage cp.async pipeline over K.
// ============================================================================
__global__ void __launch_bounds__(256, 1)
gemm_xg_mma(const float* __restrict__ b1, const float* __restrict__ b2)
{
    extern __shared__ char dynsmem[];
    __shared__ float s_bias[BN];

    const int tid    = threadIdx.x;
    const int lane   = tid & 31;
    const int wid    = tid >> 5;
    const int warp_m = wid >> 2;            // 0..1
    const int warp_n = wid & 3;             // 0..3
    const int mw     = warp_m * 64;
    const int nb     = warp_n * 32;
    const int n0     = blockIdx.x * BN;
    const int m0     = blockIdx.y * BM;

    const uint32_t sm0 = smem_u32(dynsmem);

    if (tid < BN) s_bias[tid] = b1[n0 + tid] + b2[n0 + tid];

    const __half* gA = g_xh + (size_t)m0 * IDIM;
    const __half* gB = g_wh + (size_t)n0 * IDIM;

    auto load_chunk = [&](int kc) {
        const uint32_t base = sm0 + (uint32_t)(kc & (STAGES - 1)) * STG_B;
        const int k0 = kc * BK;
#pragma unroll
        for (int part = 0; part < 4; ++part) {
            const int idx = part * 256 + tid;           // 0..1023
            const int row = (idx >> 2) & 127;
            const int seg = idx & 3;
            const uint32_t doff = (uint32_t)(row * (APAD * 2) + seg * 16);
            if (idx < 512)
                cp_async16(base + doff, gA + (size_t)row * IDIM + k0 + seg * 8);
            else
                cp_async16(base + STG_A + doff, gB + (size_t)row * IDIM + k0 + seg * 8);
        }
        asm volatile("cp.async.commit_group;" ::: "memory");
    };

    float acc[4][4][4];
#pragma unroll
    for (int mi = 0; mi < 4; ++mi)
#pragma unroll
        for (int ni = 0; ni < 4; ++ni)
#pragma unroll
            for (int q = 0; q < 4; ++q) acc[mi][ni][q] = 0.f;

    load_chunk(0);
    load_chunk(1);
    load_chunk(2);

    for (int kc = 0; kc < NCH; ++kc) {
        const int pf = kc + STAGES - 1;
        if (pf < NCH) load_chunk(pf);

        if (kc <= NCH - STAGES)
            asm volatile("cp.async.wait_group %0;" :: "n"(STAGES - 1) : "memory");
        else if (kc == NCH - 3)
            asm volatile("cp.async.wait_group 2;" ::: "memory");
        else if (kc == NCH - 2)
            asm volatile("cp.async.wait_group 1;" ::: "memory");
        else
            asm volatile("cp.async.wait_group 0;" ::: "memory");
        __syncthreads();

        const uint32_t as_ = sm0 + (uint32_t)(kc & (STAGES - 1)) * STG_B;
        const uint32_t bs_ = as_ + STG_A;

#pragma unroll
        for (int s = 0; s < 2; ++s) {               // two k16 steps
            uint32_t af[4][4];
#pragma unroll
            for (int mi = 0; mi < 4; ++mi) {
                const uint32_t addr = as_
                    + (uint32_t)(mw + mi * 16 + (lane & 15)) * (APAD * 2)
                    + (uint32_t)(s * 16 + ((lane >> 4) << 3)) * 2;
                ldmatrix_x4(af[mi], addr);
            }
            uint32_t bf[2][4];
#pragma unroll
            for (int g = 0; g < 2; ++g) {
                const uint32_t addr = bs_
                    + (uint32_t)(nb + g * 16 + (lane & 7) + (((lane >> 4) & 1) << 3)) * (APAD * 2)
                    + (uint32_t)(s * 16 + (((lane >> 3) & 1) << 3)) * 2;
                ldmatrix_x4(bf[g], addr);
            }
#pragma unroll
            for (int mi = 0; mi < 4; ++mi)
#pragma unroll
                for (int ni = 0; ni < 4; ++ni)
                    mma16816(acc[mi][ni], af[mi],
                             bf[ni >> 1][(ni & 1) * 2],
                             bf[ni >> 1][(ni & 1) * 2 + 1]);
        }
        __syncthreads();
    }

#pragma unroll
    for (int mi = 0; mi < 4; ++mi) {
        const int r0 = m0 + mw + mi * 16 + (lane >> 2);
#pragma unroll
        for (int ni = 0; ni < 4; ++ni) {
            const int c = nb + ni * 8 + (lane & 3) * 2;
            const float bb0 = s_bias[c];
            const float bb1 = s_bias[c + 1];
            float2 v0, v1;
            v0.x = acc[mi][ni][0] + bb0; v0.y = acc[mi][ni][1] + bb1;
            v1.x = acc[mi][ni][2] + bb0; v1.y = acc[mi][ni][3] + bb1;
            *(float2*)&g_xg[(size_t)r0 * GROWS + n0 + c]       = v0;
            *(float2*)&g_xg[(size_t)(r0 + 8) * GROWS + n0 + c] = v1;
        }
    }
}

// ============================================================================
// Kernel 2: persistent LSTM recurrence. W_hh fp16 in SMEM, h broadcast via
// global, central atomic + single-spinner barrier (round-3 proven), 16 warps.
// ============================================================================
__global__ void __launch_bounds__(RTHREADS, 1)
lstm_persistent(const float* __restrict__ W_hh)
{
    extern __shared__ __half sw[];
    __shared__ float s_gate[MAXROWS];
    __shared__ float s_c[UPC];

    const int tid  = threadIdx.x;
    const int wid  = tid >> 5;
    const int lane = tid & 31;
    const int cta  = blockIdx.x;
    const int u0   = cta * UPC;
    const int nu   = (HDIM - u0 < UPC) ? (HDIM - u0) : UPC;
    const int nrows = 4 * nu;

    // one-time: W_hh rows -> SMEM fp16
    for (int e = tid * 4; e < nrows * HDIM; e += RTHREADS * 4) {
        int r    = e / HDIM;
        int k    = e - r * HDIM;
        int gate = r / nu;
        int u    = r - gate * nu;
        const float4 v = *(const float4*)&W_hh[(size_t)(gate * HDIM + u0 + u) * HDIM + k];
        __half2* dst = (__half2*)&sw[r * HDIM + k];
        dst[0] = __floats2half2_rn(v.x, v.y);
        dst[1] = __floats2half2_rn(v.z, v.w);
    }
    if (tid < UPC)     s_c[tid]    = 0.f;
    if (tid < MAXROWS) s_gate[tid] = 0.f;

    unsigned base = 0u;
    if (tid == 0) base = *(volatile unsigned*)&g_base;
    __syncthreads();

    for (int t = 0; t < SEQ; ++t) {
        // prefetch xg (independent of h)
        float xgv0 = 0.f, xgv1 = 0.f, xgv2 = 0.f, xgv3 = 0.f;
        if (tid < nu) {
            const float* xp = g_xg + (size_t)t * GROWS + u0 + tid;
            xgv0 = xp[0 * HDIM];
            xgv1 = xp[1 * HDIM];
            xgv2 = xp[2 * HDIM];
            xgv3 = xp[3 * HDIM];
        }

        if (t > 0) {
            __syncthreads();   // all of step t-1's h writes done CTA-wide
            if (tid == 0) {
                __threadfence();                       // release our h slice
                atomicAdd(&g_bar, 1u);
                unsigned tgt = base + (unsigned)NCTA * (unsigned)t;
                while ((int)(*(volatile unsigned*)&g_bar - tgt) < 0) { }
                __threadfence();                       // acquire + fresh L1
            }
            __syncthreads();

            // load full h into registers (L1-shared across warps)
            float hreg[64];
            const float* hb = g_h[t & 1];
#pragma unroll
            for (int c = 0; c < 8; ++c) {
                const float4 v0 = *(const float4*)&hb[c * 256 + lane * 8];
                const float4 v1 = *(const float4*)&hb[c * 256 + lane * 8 + 4];
                hreg[c * 8 + 0] = v0.x; hreg[c * 8 + 1] = v0.y;
                hreg[c * 8 + 2] = v0.z; hreg[c * 8 + 3] = v0.w;
                hreg[c * 8 + 4] = v1.x; hreg[c * 8 + 5] = v1.y;
                hreg[c * 8 + 6] = v1.z; hreg[c * 8 + 7] = v1.w;
            }

            for (int r = wid; r < nrows; r += NWARP) {
                const __half* wr = sw + r * HDIM;
                float a0 = 0.f, a1 = 0.f, a2 = 0.f, a3 = 0.f;
#pragma unroll
                for (int c = 0; c < 8; ++c) {
                    const uint4 wv = *(const uint4*)(wr + c * 256 + lane * 8);
                    const __half2 p0 = *reinterpret_cast<const __half2*>(&wv.x);
                    const __half2 p1 = *reinterpret_cast<const __half2*>(&wv.y);
                    const __half2 p2 = *reinterpret_cast<const __half2*>(&wv.z);
                    const __half2 p3 = *reinterpret_cast<const __half2*>(&wv.w);
                    float2 f;
                    f = __half22float2(p0);
                    a0 = fmaf(f.x, hreg[c * 8 + 0], a0);
                    a1 = fmaf(f.y, hreg[c * 8 + 1], a1);
                    f = __half22float2(p1);
                    a2 = fmaf(f.x, hreg[c * 8 + 2], a2);
                    a3 = fmaf(f.y, hreg[c * 8 + 3], a3);
                    f = __half22float2(p2);
                    a0 = fmaf(f.x, hreg[c * 8 + 4], a0);
                    a1 = fmaf(f.y, hreg[c * 8 + 5], a1);
                    f = __half22float2(p3);
                    a2 = fmaf(f.x, hreg[c * 8 + 6], a2);
                    a3 = fmaf(f.y, hreg[c * 8 + 7], a3);
                }
                float acc = (a0 + a1) + (a2 + a3);
#pragma unroll
                for (int off = 16; off; off >>= 1)
                    acc += __shfl_xor_sync(0xffffffffu, acc, off);
                if (lane == 0) s_gate[r] = acc;
            }
        }
        __syncthreads();

        if (tid < nu) {
            const float gi = xgv0 + s_gate[0 * nu + tid];
            const float gf = xgv1 + s_gate[1 * nu + tid];
            const float gg = xgv2 + s_gate[2 * nu + tid];
            const float go = xgv3 + s_gate[3 * nu + tid];
            const float ig = 1.f / (1.f + expf(-gi));
            const float fg = 1.f / (1.f + expf(-gf));
            const float g2 = tanhf(gg);
            const float og = 1.f / (1.f + expf(-go));
            const float cc = fg * s_c[tid] + ig * g2;
            s_c[tid] = cc;
            g_h[(t + 1) & 1][u0 + tid] = og * tanhf(cc);
        }
    }

    // final barrier: safe epoch-base update for the next graph replay
    __syncthreads();
    if (tid == 0) {
        __threadfence();
        atomicAdd(&g_bar, 1u);
        unsigned tgt = base + (unsigned)NCTA * (unsigned)SEQ;
        while ((int)(*(volatile unsigned*)&g_bar - tgt) < 0) { }
        if (cta == 0) *(volatile unsigned*)&g_base = tgt;
    }
}

// ============================================================================
// Kernel 3: out = h_last @ W_fc^T + b_fc   (h_last in g_h[0]; SEQ even)
// ============================================================================
__global__ void __launch_bounds__(256)
fc_kernel(const float* __restrict__ Wfc, const float* __restrict__ bfc,
          float* __restrict__ out)
{
    const int o    = blockIdx.x * 8 + (threadIdx.x >> 5);
    const int lane = threadIdx.x & 31;
    const float* hb = g_h[0];
    const float* wr = Wfc + (size_t)o * HDIM;
    float acc = 0.f;
#pragma unroll
    for (int i = 0; i < 16; ++i) {
        const int k = i * 128 + lane * 4;
        const float4 w  = *(const float4*)&wr[k];
        const float4 h4 = *(const float4*)&hb[k];
        acc += w.x * h4.x + w.y * h4.y + w.z * h4.z + w.w * h4.w;
    }
#pragma unroll
    for (int off = 16; off; off >>= 1)
        acc += __shfl_xor_sync(0xffffffffu, acc, off);
    if (lane == 0) out[o] = acc + bfc[o];
}

// ============================================================================
extern "C" void kernel_launch(void* const* d_in, const int* in_sizes, int n_in,
                              void* d_out, int out_size)
{
    const float* x   = (const float*)d_in[0];
    const float* Wih = (const float*)d_in[1];
    const float* Whh = (const float*)d_in[2];
    const float* bih = (const float*)d_in[3];
    const float* bhh = (const float*)d_in[4];
    const float* Wfc = (const float*)d_in[5];
    const float* bfc = (const float*)d_in[6];
    float* out = (float*)d_out;

    static __half* p_xh = nullptr;
    static __half* p_wh = nullptr;
    if (!p_xh) {
        cudaGetSymbolAddress((void**)&p_xh, g_xh);
        cudaGetSymbolAddress((void**)&p_wh, g_wh);
        cudaFuncSetAttribute(gemm_xg_mma,
                             cudaFuncAttributeMaxDynamicSharedMemorySize,
                             (int)GEMM_SMEM);
        cudaFuncSetAttribute(lstm_persistent,
                             cudaFuncAttributeMaxDynamicSharedMemorySize,
                             (int)SW_BYTES);
    }

    f2h_kernel<<<(SEQ * IDIM / 8 + 255) / 256, 256>>>(x, p_xh, SEQ * IDIM);
    f2h_kernel<<<(GROWS * IDIM / 8 + 255) / 256, 256>>>(Wih, p_wh, GROWS * IDIM);
    gemm_xg_mma<<<dim3(GROWS / BN, SEQ / BM), 256, GEMM_SMEM>>>(bih, bhh);
    lstm_persistent<<<NCTA, RTHREADS, SW_BYTES>>>(Whh);
    fc_kernel<<<OUTD / 8, 256>>>(Wfc, bfc, out);
}

// round 9
// speedup vs baseline: 1.3287x; 1.0363x over previous
#include <cuda_runtime.h>
#include <cuda_fp16.h>
#include <math.h>
#include <stdint.h>

// Problem dims
#define SEQ    4096
#define IDIM   2048
#define HDIM   2048
#define GROWS  8192   // 4*HDIM, PyTorch gate order i,f,g,o
#define OUTD   2048

// Persistent recurrence kernel config
#define UPC      14
#define NCTA     147
#define RTHREADS 1024             // 32 warps: 4 k-groups x 8 row-groups
#define MAXROWS  (4*UPC)
#define SW_BYTES (MAXROWS*HDIM*sizeof(__half))   // 229376 B

// mma.sync GEMM config
#define BM 128
#define BN 128
#define BK 32
#define NCH    (IDIM/BK)          // 64 k-chunks
#define STAGES 4
#define APAD   40                 // halves per SMEM row (32 + 8 pad) -> 80B stride
#define STG_A  (BM*APAD*2)        // 10240 B
#define STG_B  (2*STG_A)          // 20480 B per stage (A then B)
#define GEMM_SMEM (STAGES*STG_B)  // 81920 B

// -------- device scratch (static allocation only) --------
__device__ float    g_xg[(size_t)SEQ * GROWS];   // 128 MB
__device__ __half   g_xh[(size_t)SEQ * IDIM];    // 16 MB  x in fp16
__device__ __half   g_wh[(size_t)GROWS * IDIM];  // 32 MB  W_ih in fp16
__device__ float    g_h[2][HDIM];
__device__ unsigned g_bar  = 0u;                 // monotonic arrival counter
__device__ unsigned g_base = 0u;                 // epoch base across graph replays

// ---------------- PTX helpers (all sm_80+; no arch-suffix features) ----------
__device__ __forceinline__ uint32_t smem_u32(const void* p) {
    return (uint32_t)__cvta_generic_to_shared(p);
}
__device__ __forceinline__ void cp_async16(uint32_t dst, const void* src) {
    asm volatile("cp.async.cg.shared.global [%0], [%1], 16;" :: "r"(dst), "l"(src));
}
__device__ __forceinline__ void ldmatrix_x4(uint32_t* r, uint32_t addr) {
    asm volatile("ldmatrix.sync.aligned.m8n8.x4.shared.b16 {%0,%1,%2,%3}, [%4];"
                 : "=r"(r[0]), "=r"(r[1]), "=r"(r[2]), "=r"(r[3]) : "r"(addr));
}
__device__ __forceinline__ void mma16816(float* c, const uint32_t* a,
                                         uint32_t b0, uint32_t b1) {
    asm volatile(
        "mma.sync.aligned.m16n8k16.row.col.f32.f16.f16.f32 "
        "{%0,%1,%2,%3}, {%4,%5,%6,%7}, {%8,%9}, {%0,%1,%2,%3};"
        : "+f"(c[0]), "+f"(c[1]), "+f"(c[2]), "+f"(c[3])
        : "r"(a[0]), "r"(a[1]), "r"(a[2]), "r"(a[3]), "r"(b0), "r"(b1));
}

// ============================================================================
// Kernel 0: fp32 -> fp16 conversion (x and W_ih)
// ============================================================================
__global__ void __launch_bounds__(256)
f2h_kernel(const float* __restrict__ src, __half* __restrict__ dst, int n)
{
    int i = (blockIdx.x * 256 + threadIdx.x) * 8;
    if (i >= n) return;
    const float4 a = *(const float4*)(src + i);
    const float4 b = *(const float4*)(src + i + 4);
    __half2 h0 = __floats2half2_rn(a.x, a.y);
    __half2 h1 = __floats2half2_rn(a.z, a.w);
    __half2 h2 = __floats2half2_rn(b.x, b.y);
    __half2 h3 = __floats2half2_rn(b.z, b.w);
    uint4 o;
    o.x = *(uint32_t*)&h0; o.y = *(uint32_t*)&h1;
    o.z = *(uint32_t*)&h2; o.w = *(uint32_t*)&h3;
    *(uint4*)(dst + i) = o;
}

// ============================================================================
// Kernel 1: xg = x @ W_ih^T + b_ih + b_hh  via mma.sync.m16n8k16 (fp16->fp32).
// 128x128 tile / CTA, 8 warps of 64x32, 4-stage cp.async pipeline over K.
// ============================================================================
__global__ void __launch_bounds__(256, 1)
gemm_xg_mma(const float* __restrict__ b1, const float* __restrict__ b2)
{
    extern __shared__ char dynsmem[];
    __shared__ float s_bias[BN];

    const int tid    = threadIdx.x;
    const int lane   = tid & 31;
    const int wid    = tid >> 5;
    const int warp_m = wid >> 2;            // 0..1
    const int warp_n = wid & 3;             // 0..3
    const int mw     = warp_m * 64;
    const int nb     = warp_n * 32;
    const int n0     = blockIdx.x * BN;
    const int m0     = blockIdx.y * BM;

    const uint32_t sm0 = smem_u32(dynsmem);

    if (tid < BN) s_bias[tid] = b1[n0 + tid] + b2[n0 + tid];

    const __half* gA = g_xh + (size_t)m0 * IDIM;
    const __half* gB = g_wh + (size_t)n0 * IDIM;

    auto load_chunk = [&](int kc) {
        const uint32_t base = sm0 + (uint32_t)(kc & (STAGES - 1)) * STG_B;
        const int k0 = kc * BK;
#pragma unroll
        for (int part = 0; part < 4; ++part) {
            const int idx = part * 256 + tid;           // 0..1023
            const int row = (idx >> 2) & 127;
            const int seg = idx & 3;
            const uint32_t doff = (uint32_t)(row * (APAD * 2) + seg * 16);
            if (idx < 512)
                cp_async16(base + doff, gA + (size_t)row * IDIM + k0 + seg * 8);
            else
                cp_async16(base + STG_A + doff, gB + (size_t)row * IDIM + k0 + seg * 8);
        }
        asm volatile("cp.async.commit_group;" ::: "memory");
    };

    float acc[4][4][4];
#pragma unroll
    for (int mi = 0; mi < 4; ++mi)
#pragma unroll
        for (int ni = 0; ni < 4; ++ni)
#pragma unroll
            for (int q = 0; q < 4; ++q) acc[mi][ni][q] = 0.f;

    load_chunk(0);
    load_chunk(1);
    load_chunk(2);

    for (int kc = 0; kc < NCH; ++kc) {
        const int pf = kc + STAGES - 1;
        if (pf < NCH) load_chunk(pf);

        if (kc <= NCH - STAGES)
            asm volatile("cp.async.wait_group %0;" :: "n"(STAGES - 1) : "memory");
        else if (kc == NCH - 3)
            asm volatile("cp.async.wait_group 2;" ::: "memory");
        else if (kc == NCH - 2)
            asm volatile("cp.async.wait_group 1;" ::: "memory");
        else
            asm volatile("cp.async.wait_group 0;" ::: "memory");
        __syncthreads();

        const uint32_t as_ = sm0 + (uint32_t)(kc & (STAGES - 1)) * STG_B;
        const uint32_t bs_ = as_ + STG_A;

#pragma unroll
        for (int s = 0; s < 2; ++s) {               // two k16 steps
            uint32_t af[4][4];
#pragma unroll
            for (int mi = 0; mi < 4; ++mi) {
                const uint32_t addr = as_
                    + (uint32_t)(mw + mi * 16 + (lane & 15)) * (APAD * 2)
                    + (uint32_t)(s * 16 + ((lane >> 4) << 3)) * 2;
                ldmatrix_x4(af[mi], addr);
            }
            uint32_t bf[2][4];
#pragma unroll
            for (int g = 0; g < 2; ++g) {
                const uint32_t addr = bs_
                    + (uint32_t)(nb + g * 16 + (lane & 7) + (((lane >> 4) & 1) << 3)) * (APAD * 2)
                    + (uint32_t)(s * 16 + (((lane >> 3) & 1) << 3)) * 2;
                ldmatrix_x4(bf[g], addr);
            }
#pragma unroll
            for (int mi = 0; mi < 4; ++mi)
#pragma unroll
                for (int ni = 0; ni < 4; ++ni)
                    mma16816(acc[mi][ni], af[mi],
                             bf[ni >> 1][(ni & 1) * 2],
                             bf[ni >> 1][(ni & 1) * 2 + 1]);
        }
        __syncthreads();
    }

#pragma unroll
    for (int mi = 0; mi < 4; ++mi) {
        const int r0 = m0 + mw + mi * 16 + (lane >> 2);
#pragma unroll
        for (int ni = 0; ni < 4; ++ni) {
            const int c = nb + ni * 8 + (lane & 3) * 2;
            const float bb0 = s_bias[c];
            const float bb1 = s_bias[c + 1];
            float2 v0, v1;
            v0.x = acc[mi][ni][0] + bb0; v0.y = acc[mi][ni][1] + bb1;
            v1.x = acc[mi][ni][2] + bb0; v1.y = acc[mi][ni][3] + bb1;
            *(float2*)&g_xg[(size_t)r0 * GROWS + n0 + c]       = v0;
            *(float2*)&g_xg[(size_t)(r0 + 8) * GROWS + n0 + c] = v1;
        }
    }
}

// ============================================================================
// Kernel 2: persistent LSTM recurrence, 32 warps = 4 k-groups x 8 row-groups.
// Warp (kgrp,rgrp): k-slice of 512 (two contiguous 256-half blocks, conflict-
// free at lane*8 stride), rows rgrp, rgrp+8, ... (7 rows). Partial dots land
// in s_part[row] (float4, one lane-0 write per kgrp); gate-combine sums them.
// Central atomic + single-spinner global barrier (proven).
// ============================================================================
__global__ void __launch_bounds__(RTHREADS, 1)
lstm_persistent(const float* __restrict__ W_hh)
{
    extern __shared__ __half sw[];
    __shared__ float4 s_part[MAXROWS];    // [row] -> 4 kgrp partials
    __shared__ float  s_c[UPC];

    const int tid   = threadIdx.x;
    const int wid   = tid >> 5;
    const int lane  = tid & 31;
    const int kgrp  = wid >> 3;           // 0..3
    const int rgrp  = wid & 7;            // 0..7
    const int cta   = blockIdx.x;
    const int u0    = cta * UPC;
    const int nu    = (HDIM - u0 < UPC) ? (HDIM - u0) : UPC;
    const int nrows = 4 * nu;
    const int kbase = kgrp * 512;         // halves
    const int koff  = kbase + lane * 8;   // first 256-half block, lane slice

    // one-time: W_hh rows -> SMEM fp16
    for (int e = tid * 4; e < nrows * HDIM; e += RTHREADS * 4) {
        int r    = e / HDIM;
        int k    = e - r * HDIM;
        int gate = r / nu;
        int u    = r - gate * nu;
        const float4 v = *(const float4*)&W_hh[(size_t)(gate * HDIM + u0 + u) * HDIM + k];
        __half2* dst = (__half2*)&sw[r * HDIM + k];
        dst[0] = __floats2half2_rn(v.x, v.y);
        dst[1] = __floats2half2_rn(v.z, v.w);
    }
    if (tid < UPC)     s_c[tid]    = 0.f;
    if (tid < MAXROWS) s_part[tid] = make_float4(0.f, 0.f, 0.f, 0.f);

    unsigned base = 0u;
    if (tid == 0) base = *(volatile unsigned*)&g_base;
    __syncthreads();

    for (int t = 0; t < SEQ; ++t) {
        // prefetch xg (independent of h)
        float xgv0 = 0.f, xgv1 = 0.f, xgv2 = 0.f, xgv3 = 0.f;
        if (tid < nu) {
            const float* xp = g_xg + (size_t)t * GROWS + u0 + tid;
            xgv0 = xp[0 * HDIM];
            xgv1 = xp[1 * HDIM];
            xgv2 = xp[2 * HDIM];
            xgv3 = xp[3 * HDIM];
        }

        if (t > 0) {
            __syncthreads();   // (A) all of step t-1's h/s_part use finished
            if (tid == 0) {
                __threadfence();                       // release our h slice
                atomicAdd(&g_bar, 1u);
                unsigned tgt = base + (unsigned)NCTA * (unsigned)t;
                while ((int)(*(volatile unsigned*)&g_bar - tgt) < 0) { }
                __threadfence();                       // acquire + fresh L1
            }
            __syncthreads();   // (B)

            // h slice for this warp's k-range: 16 floats (2 blocks of 8)
            const float* hb = g_h[t & 1];
            const float4 h0 = *(const float4*)&hb[koff];
            const float4 h1 = *(const float4*)&hb[koff + 4];
            const float4 h2 = *(const float4*)&hb[koff + 256];
            const float4 h3 = *(const float4*)&hb[koff + 260];

            for (int r = rgrp; r < nrows; r += 8) {
                const __half* wr = sw + r * HDIM + koff;
                const uint4 wv0 = *(const uint4*)(wr);
                const uint4 wv1 = *(const uint4*)(wr + 256);
                float a0, a1;
                float2 f;
                f  = __half22float2(*reinterpret_cast<const __half2*>(&wv0.x));
                a0 = f.x * h0.x;            a1 = f.y * h0.y;
                f  = __half22float2(*reinterpret_cast<const __half2*>(&wv0.y));
                a0 = fmaf(f.x, h0.z, a0);   a1 = fmaf(f.y, h0.w, a1);
                f  = __half22float2(*reinterpret_cast<const __half2*>(&wv0.z));
                a0 = fmaf(f.x, h1.x, a0);   a1 = fmaf(f.y, h1.y, a1);
                f  = __half22float2(*reinterpret_cast<const __half2*>(&wv0.w));
                a0 = fmaf(f.x, h1.z, a0);   a1 = fmaf(f.y, h1.w, a1);
                f  = __half22float2(*reinterpret_cast<const __half2*>(&wv1.x));
                a0 = fmaf(f.x, h2.x, a0);   a1 = fmaf(f.y, h2.y, a1);
                f  = __half22float2(*reinterpret_cast<const __half2*>(&wv1.y));
                a0 = fmaf(f.x, h2.z, a0);   a1 = fmaf(f.y, h2.w, a1);
                f  = __half22float2(*reinterpret_cast<const __half2*>(&wv1.z));
                a0 = fmaf(f.x, h3.x, a0);   a1 = fmaf(f.y, h3.y, a1);
                f  = __half22float2(*reinterpret_cast<const __half2*>(&wv1.w));
                a0 = fmaf(f.x, h3.z, a0);   a1 = fmaf(f.y, h3.w, a1);

                float acc = a0 + a1;
#pragma unroll
                for (int off = 16; off; off >>= 1)
                    acc += __shfl_xor_sync(0xffffffffu, acc, off);
                if (lane == 0) ((float*)&s_part[r])[kgrp] = acc;
            }
        }
        __syncthreads();       // (C) s_part complete

        if (tid < nu) {
            const float4 pi = s_part[0 * nu + tid];
            const float4 pf = s_part[1 * nu + tid];
            const float4 pg = s_part[2 * nu + tid];
            const float4 po = s_part[3 * nu + tid];
            const float gi = xgv0 + (pi.x + pi.y) + (pi.z + pi.w);
            const float gf = xgv1 + (pf.x + pf.y) + (pf.z + pf.w);
            const float gg = xgv2 + (pg.x + pg.y) + (pg.z + pg.w);
            const float go = xgv3 + (po.x + po.y) + (po.z + po.w);
            const float ig = 1.f / (1.f + expf(-gi));
            const float fg = 1.f / (1.f + expf(-gf));
            const float g2 = tanhf(gg);
            const float og = 1.f / (1.f + expf(-go));
            const float cc = fg * s_c[tid] + ig * g2;
            s_c[tid] = cc;
            g_h[(t + 1) & 1][u0 + tid] = og * tanhf(cc);
        }
    }

    // final barrier: safe epoch-base update for the next graph replay
    __syncthreads();
    if (tid == 0) {
        __threadfence();
        atomicAdd(&g_bar, 1u);
        unsigned tgt = base + (unsigned)NCTA * (unsigned)SEQ;
        while ((int)(*(volatile unsigned*)&g_bar - tgt) < 0) { }
        if (cta == 0) *(volatile unsigned*)&g_base = tgt;
    }
}

// ============================================================================
// Kernel 3: out = h_last @ W_fc^T + b_fc   (h_last in g_h[0]; SEQ even)
// ============================================================================
__global__ void __launch_bounds__(256)
fc_kernel(const float* __restrict__ Wfc, const float* __restrict__ bfc,
          float* __restrict__ out)
{
    const int o    = blockIdx.x * 8 + (threadIdx.x >> 5);
    const int lane = threadIdx.x & 31;
    const float* hb = g_h[0];
    const float* wr = Wfc + (size_t)o * HDIM;
    float acc = 0.f;
#pragma unroll
    for (int i = 0; i < 16; ++i) {
        const int k = i * 128 + lane * 4;
        const float4 w  = *(const float4*)&wr[k];
        const float4 h4 = *(const float4*)&hb[k];
        acc += w.x * h4.x + w.y * h4.y + w.z * h4.z + w.w * h4.w;
    }
#pragma unroll
    for (int off = 16; off; off >>= 1)
        acc += __shfl_xor_sync(0xffffffffu, acc, off);
    if (lane == 0) out[o] = acc + bfc[o];
}

// ============================================================================
extern "C" void kernel_launch(void* const* d_in, const int* in_sizes, int n_in,
                              void* d_out, int out_size)
{
    const float* x   = (const float*)d_in[0];
    const float* Wih = (const float*)d_in[1];
    const float* Whh = (const float*)d_in[2];
    const float* bih = (const float*)d_in[3];
    const float* bhh = (const float*)d_in[4];
    const float* Wfc = (const float*)d_in[5];
    const float* bfc = (const float*)d_in[6];
    float* out = (float*)d_out;

    static __half* p_xh = nullptr;
    static __half* p_wh = nullptr;
    if (!p_xh) {
        cudaGetSymbolAddress((void**)&p_xh, g_xh);
        cudaGetSymbolAddress((void**)&p_wh, g_wh);
        cudaFuncSetAttribute(gemm_xg_mma,
                             cudaFuncAttributeMaxDynamicSharedMemorySize,
                             (int)GEMM_SMEM);
        cudaFuncSetAttribute(lstm_persistent,
                             cudaFuncAttributeMaxDynamicSharedMemorySize,
                             (int)SW_BYTES);
    }

    f2h_kernel<<<(SEQ * IDIM / 8 + 255) / 256, 256>>>(x, p_xh, SEQ * IDIM);
    f2h_kernel<<<(GROWS * IDIM / 8 + 255) / 256, 256>>>(Wih, p_wh, GROWS * IDIM);
    gemm_xg_mma<<<dim3(GROWS / BN, SEQ / BM), 256, GEMM_SMEM>>>(bih, bhh);
    lstm_persistent<<<NCTA, RTHREADS, SW_BYTES>>>(Whh);
    fc_kernel<<<OUTD / 8, 256>>>(Wfc, bfc, out);
}